// round 3
// baseline (speedup 1.0000x reference)
#include <cuda_runtime.h>
#include <cuda_bf16.h>

#define NV 32000
#define NB 64
#define NL 1024
#define NH 128

// scratch (no allocs allowed)
__device__ float g_tab[NV * NH];   // [v][128]: ks in 0..63, ke in 64..127
__device__ float g_r[NB * NH];     // [b][128]

// ============================================================================
// K1: vocab table.  Per CTA: 64 vocab rows, 256 threads.
//   E -> T1 = relu(E@W1^T+b1) -> X = E + T1@W2^T + b2 -> LN -> KK = HLN@Wk^T
// smem layout (floats), stride 65 (odd => conflict-free transposed staging)
// ============================================================================
#define K1_ST   65
#define K1_BS   (128 * K1_ST)
#define K1_T1   (K1_BS + 256 * K1_ST)
#define K1_RED  (K1_T1 + 256 * K1_ST)
#define K1_SMEMF (K1_RED + 512)

__global__ void __launch_bounds__(256, 1)
k1_kernel(const float* __restrict__ embed,
          const float* __restrict__ W1, const float* __restrict__ b1,
          const float* __restrict__ W2, const float* __restrict__ b2,
          const float* __restrict__ gamma, const float* __restrict__ beta,
          const float* __restrict__ Wsem, const float* __restrict__ Wepi)
{
    extern __shared__ float sm[];
    float* As  = sm;            // [k(0..127)][65] : E, then X, then HLN (A-operand)
    float* Bs  = sm + K1_BS;    // [k(0..255)][65] : weight panel (B-operand)
    float* T1s = sm + K1_T1;    // [k(0..255)][65] : T1 (A-operand of phase B)
    float* red = sm + K1_RED;   // [512] LN reduction scratch

    const int tid = threadIdx.x;
    const int v0  = blockIdx.x * 64;
    const int ty  = tid >> 4, tx = tid & 15;

    // stage E (transposed, k-major)
    for (int idx = tid; idx < 64 * 128; idx += 256) {
        int r = idx >> 7, h = idx & 127;
        As[h * K1_ST + r] = __ldg(&embed[(size_t)(v0 + r) * NH + h]);
    }
    __syncthreads();

    // ---- Phase A: T1 = relu(E @ W1^T + b1), 4 col panels of 64 ----
    for (int p = 0; p < 4; p++) {
        for (int idx = tid; idx < 64 * 128; idx += 256) {
            int c = idx >> 7, k = idx & 127;
            Bs[k * K1_ST + c] = __ldg(&W1[(p * 64 + c) * NH + k]);
        }
        __syncthreads();
        float acc[4][4];
        #pragma unroll
        for (int i = 0; i < 4; i++)
            #pragma unroll
            for (int j = 0; j < 4; j++) acc[i][j] = 0.f;
        #pragma unroll 8
        for (int k = 0; k < 128; k++) {
            float a[4], b[4];
            #pragma unroll
            for (int i = 0; i < 4; i++) a[i] = As[k * K1_ST + 4 * ty + i];
            #pragma unroll
            for (int j = 0; j < 4; j++) b[j] = Bs[k * K1_ST + 4 * tx + j];
            #pragma unroll
            for (int i = 0; i < 4; i++)
                #pragma unroll
                for (int j = 0; j < 4; j++) acc[i][j] += a[i] * b[j];
        }
        #pragma unroll
        for (int j = 0; j < 4; j++) {
            float bj = __ldg(&b1[p * 64 + 4 * tx + j]);
            #pragma unroll
            for (int i = 0; i < 4; i++)
                T1s[(p * 64 + 4 * tx + j) * K1_ST + 4 * ty + i] =
                    fmaxf(acc[i][j] + bj, 0.f);
        }
        __syncthreads();
    }

    // ---- Phase B: X = E + T1 @ W2^T + b2 (in place into As), 2 panels ----
    for (int p = 0; p < 2; p++) {
        for (int idx = tid; idx < 64 * 256; idx += 256) {
            int c = idx >> 8, k = idx & 255;
            Bs[k * K1_ST + c] = __ldg(&W2[(p * 64 + c) * 256 + k]);
        }
        __syncthreads();
        float acc[4][4];
        #pragma unroll
        for (int i = 0; i < 4; i++)
            #pragma unroll
            for (int j = 0; j < 4; j++) acc[i][j] = 0.f;
        #pragma unroll 8
        for (int k = 0; k < 256; k++) {
            float a[4], b[4];
            #pragma unroll
            for (int i = 0; i < 4; i++) a[i] = T1s[k * K1_ST + 4 * ty + i];
            #pragma unroll
            for (int j = 0; j < 4; j++) b[j] = Bs[k * K1_ST + 4 * tx + j];
            #pragma unroll
            for (int i = 0; i < 4; i++)
                #pragma unroll
                for (int j = 0; j < 4; j++) acc[i][j] += a[i] * b[j];
        }
        #pragma unroll
        for (int j = 0; j < 4; j++) {
            float bj = __ldg(&b2[p * 64 + 4 * tx + j]);
            #pragma unroll
            for (int i = 0; i < 4; i++) {
                int h = p * 64 + 4 * tx + j;
                As[h * K1_ST + 4 * ty + i] += acc[i][j] + bj;
            }
        }
        __syncthreads();
    }

    // ---- LayerNorm (in place, population var) ----
    {
        int r = tid & 63, qq = tid >> 6;
        float s1 = 0.f, s2 = 0.f;
        #pragma unroll 8
        for (int hh = 0; hh < 32; hh++) {
            float x = As[(qq * 32 + hh) * K1_ST + r];
            s1 += x; s2 += x * x;
        }
        red[qq * 64 + r]       = s1;
        red[256 + qq * 64 + r] = s2;
        __syncthreads();
        float S1 = red[r] + red[64 + r] + red[128 + r] + red[192 + r];
        float S2 = red[256 + r] + red[320 + r] + red[384 + r] + red[448 + r];
        float mu   = S1 * (1.f / 128.f);
        float var  = S2 * (1.f / 128.f) - mu * mu;
        float rstd = rsqrtf(var + 1e-5f);
        #pragma unroll 8
        for (int hh = 0; hh < 32; hh++) {
            int h = qq * 32 + hh;
            float x = As[h * K1_ST + r];
            As[h * K1_ST + r] = (x - mu) * rstd * __ldg(&gamma[h]) + __ldg(&beta[h]);
        }
    }
    __syncthreads();

    // ---- Phase D: KK = HLN @ Wk^T  -> g_tab ----
    for (int p = 0; p < 2; p++) {
        const float* Wk = p ? Wepi : Wsem;
        for (int idx = tid; idx < 64 * 128; idx += 256) {
            int c = idx >> 7, k = idx & 127;
            Bs[k * K1_ST + c] = __ldg(&Wk[c * NH + k]);
        }
        __syncthreads();
        float acc[4][4];
        #pragma unroll
        for (int i = 0; i < 4; i++)
            #pragma unroll
            for (int j = 0; j < 4; j++) acc[i][j] = 0.f;
        #pragma unroll 8
        for (int k = 0; k < 128; k++) {
            float a[4], b[4];
            #pragma unroll
            for (int i = 0; i < 4; i++) a[i] = As[k * K1_ST + 4 * ty + i];
            #pragma unroll
            for (int j = 0; j < 4; j++) b[j] = Bs[k * K1_ST + 4 * tx + j];
            #pragma unroll
            for (int i = 0; i < 4; i++)
                #pragma unroll
                for (int j = 0; j < 4; j++) acc[i][j] += a[i] * b[j];
        }
        #pragma unroll
        for (int i = 0; i < 4; i++) {
            float4 o;
            o.x = acc[i][0]; o.y = acc[i][1]; o.z = acc[i][2]; o.w = acc[i][3];
            *(float4*)&g_tab[(size_t)(v0 + 4 * ty + i) * NH + p * 64 + 4 * tx] = o;
        }
        __syncthreads();
    }
}

// ============================================================================
// K2: sequential gated memory scan. 64 CTAs (1/batch) x 256 threads.
// thread t: row i = t>>2, quarter q = t&3 owns M_s[i][16q..16q+15], M_e same.
// k-vector smem layout: quarter stride 20 (16B-aligned, conflict-free float4)
// SINGLE barrier per step: slot commit is to the opposite parity buffer,
// wred is parity double-buffered, so one __syncthreads covers everything.
// ============================================================================
#define KQ    20
#define KSLOT 160   // ks quarters at q*20 (0..79), ke at 80 + q*20

__global__ void __launch_bounds__(256, 1)
k2_kernel(const int* __restrict__ seq,
          const float* __restrict__ Wrp, const float* __restrict__ brp)
{
    __shared__ int   seqs[NL];
    __shared__ float slot[2 * KSLOT];
    __shared__ float wred[32];          // [parity][16]
    __shared__ float cbuf[128];

    const int tid  = threadIdx.x;
    const int b    = blockIdx.x;
    const int i    = tid >> 2, q = tid & 3;
    const int lane = tid & 31;

    for (int idx = tid; idx < NL; idx += 256) seqs[idx] = seq[b * NL + idx];
    __syncthreads();

    // preload k_0 into slot 0
    if (tid < 128) {
        int tok = seqs[0];
        float v = __ldg(&g_tab[(size_t)tok * NH + tid]);
        int part = tid >> 6, jq = (tid >> 4) & 3, jj = tid & 15;
        slot[part * 80 + jq * KQ + jj] = v;
    }
    __syncthreads();

    float ms[16], me[16];
    #pragma unroll
    for (int jj = 0; jj < 16; jj++) { ms[jj] = 0.f; me[jj] = 0.f; }

    const int ipos = (i >> 4) * KQ + (i & 15);               // pos of index i
    const int lpos = (lane >> 4) * KQ + (lane & 15);         // pos of index lane
    const int cpart = tid >> 6, cjq = (tid >> 4) & 3, cjj = tid & 15;

    for (int t = 0; t < NL - 1; t++) {
        const float* ks = &slot[(t & 1) * KSLOT];
        const float* ke = ks + 80;
        const int nt = t + 1;

        // prefetch k_{t+1}
        float pv = 0.f;
        if (tid < 128) pv = __ldg(&g_tab[(size_t)seqs[nt] * NH + tid]);

        // norms, redundantly per warp (lane sums elems lane and lane+32)
        float a1 = ks[lpos], a2 = ks[lpos + 2 * KQ];
        float e1 = ke[lpos], e2 = ke[lpos + 2 * KQ];
        float ns = a1 * a1 + a2 * a2;
        float ne = e1 * e1 + e2 * e2;
        #pragma unroll
        for (int o = 16; o; o >>= 1) {
            ns += __shfl_xor_sync(0xffffffffu, ns, o);
            ne += __shfl_xor_sync(0xffffffffu, ne, o);
        }
        float inv_s = 1.f / fmaxf(sqrtf(ns), 1e-12f);
        float inv_e = 1.f / fmaxf(sqrtf(ne), 1e-12f);

        // matvec partials over this thread's 16 columns
        float kvs[16], kve[16];
        const float* ksq = ks + q * KQ;
        const float* keq = ke + q * KQ;
        #pragma unroll
        for (int jj = 0; jj < 16; jj += 4) {
            float4 f = *(const float4*)&ksq[jj];
            kvs[jj] = f.x; kvs[jj + 1] = f.y; kvs[jj + 2] = f.z; kvs[jj + 3] = f.w;
            float4 g = *(const float4*)&keq[jj];
            kve[jj] = g.x; kve[jj + 1] = g.y; kve[jj + 2] = g.z; kve[jj + 3] = g.w;
        }
        float ps = 0.f, pe = 0.f;
        #pragma unroll
        for (int jj = 0; jj < 16; jj++) {
            ps += ms[jj] * kvs[jj];
            pe += me[jj] * kve[jj];
        }
        ps += __shfl_xor_sync(0xffffffffu, ps, 1);
        ps += __shfl_xor_sync(0xffffffffu, ps, 2);
        pe += __shfl_xor_sync(0xffffffffu, pe, 1);
        pe += __shfl_xor_sync(0xffffffffu, pe, 2);
        float ds = ks[ipos] - ps * inv_s;
        float de = ke[ipos] - pe * inv_e;

        // error norms: warp partials (64 distinct rows, q==0 lanes contribute)
        float vs = (q == 0) ? ds * ds : 0.f;
        float ve = (q == 0) ? de * de : 0.f;
        #pragma unroll
        for (int o = 16; o; o >>= 1) {
            vs += __shfl_xor_sync(0xffffffffu, vs, o);
            ve += __shfl_xor_sync(0xffffffffu, ve, o);
        }
        float* wr = &wred[(t & 1) * 16];
        if (lane == 0) { wr[tid >> 5] = vs; wr[8 + (tid >> 5)] = ve; }

        // commit prefetched k_{t+1} to the OPPOSITE parity buffer
        if (tid < 128)
            slot[(nt & 1) * KSLOT + cpart * 80 + cjq * KQ + cjj] = pv;

        __syncthreads();   // the only barrier in the step

        float es2 = 0.f, ee2 = 0.f;
        #pragma unroll
        for (int u = 0; u < 8; u++) { es2 += wr[u]; ee2 += wr[8 + u]; }
        bool fire = (sqrtf(es2) >= 0.7f * sqrtf(ns)) ||
                    (sqrtf(ee2) >= 0.7f * sqrtf(ne));

        if (fire) {  // uniform across block
            float cs = 0.05f * inv_s * ds;
            float ce = 0.05f * ((float)nt * (1.f / (float)NL)) * inv_e * de;
            #pragma unroll
            for (int jj = 0; jj < 16; jj++) {
                ms[jj] += cs * kvs[jj];
                me[jj] += ce * kve[jj];
            }
        }
    }

    // final: q-projections are the tab row of seq[b][L-1] (sits in slot 1)
    {
        const float* qs = &slot[KSLOT];        // (L-1) & 1 == 1
        const float* qe = qs + 80;
        const float* q1 = qs + q * KQ;
        const float* q2 = qe + q * KQ;
        float ps = 0.f, pe = 0.f;
        #pragma unroll
        for (int jj = 0; jj < 16; jj++) {
            ps += ms[jj] * q1[jj];
            pe += me[jj] * q2[jj];
        }
        ps += __shfl_xor_sync(0xffffffffu, ps, 1);
        ps += __shfl_xor_sync(0xffffffffu, ps, 2);
        pe += __shfl_xor_sync(0xffffffffu, pe, 1);
        pe += __shfl_xor_sync(0xffffffffu, pe, 2);
        if (q == 0) { cbuf[i] = ps; cbuf[64 + i] = pe; }
    }
    __syncthreads();

    // r = Wrp @ c + brp  -> g_r
    {
        int o = tid >> 1, h2 = tid & 1;
        const float* wr2 = &Wrp[o * NH + h2 * 64];
        const float* cc  = &cbuf[h2 * 64];
        float s = 0.f;
        #pragma unroll 8
        for (int m = 0; m < 64; m++) s += __ldg(&wr2[m]) * cc[m];
        s += __shfl_xor_sync(0xffffffffu, s, 1);
        if (h2 == 0) g_r[b * NH + o] = s + __ldg(&brp[o]);
    }
}

// ============================================================================
// K3: out[64 x 32000] = r @ Wout^T + bout.  250 CTAs, tile 64b x 128v.
// ============================================================================
#define K3_RST 65
#define K3_WST 129
#define K3_WS  (128 * K3_RST)
#define K3_SMEMF (K3_WS + 128 * K3_WST)

__global__ void __launch_bounds__(256, 2)
k3_kernel(const float* __restrict__ Wout, const float* __restrict__ bout,
          float* __restrict__ out)
{
    extern __shared__ float sm[];
    float* rs = sm;             // [k][65] : r transposed
    float* Ws = sm + K3_WS;     // [k][129]: Wout tile transposed
    const int tid = threadIdx.x;
    const int v0  = blockIdx.x * 128;
    const int ty  = tid >> 4, tx = tid & 15;

    for (int idx = tid; idx < 64 * 128; idx += 256) {
        int bb = idx >> 7, k = idx & 127;
        rs[k * K3_RST + bb] = g_r[idx];
    }
    for (int idx = tid; idx < 128 * 128; idx += 256) {
        int vv = idx >> 7, k = idx & 127;
        Ws[k * K3_WST + vv] = __ldg(&Wout[(size_t)(v0 + vv) * NH + k]);
    }
    __syncthreads();

    float acc0[4][4], acc1[4][4];
    #pragma unroll
    for (int i = 0; i < 4; i++)
        #pragma unroll
        for (int j = 0; j < 4; j++) { acc0[i][j] = 0.f; acc1[i][j] = 0.f; }

    #pragma unroll 4
    for (int k = 0; k < 128; k++) {
        float a[4], b0[4], b1[4];
        #pragma unroll
        for (int i = 0; i < 4; i++) a[i]  = rs[k * K3_RST + 4 * ty + i];
        #pragma unroll
        for (int j = 0; j < 4; j++) b0[j] = Ws[k * K3_WST + 4 * tx + j];
        #pragma unroll
        for (int j = 0; j < 4; j++) b1[j] = Ws[k * K3_WST + 64 + 4 * tx + j];
        #pragma unroll
        for (int i = 0; i < 4; i++)
            #pragma unroll
            for (int j = 0; j < 4; j++) {
                acc0[i][j] += a[i] * b0[j];
                acc1[i][j] += a[i] * b1[j];
            }
    }

    float bj0[4], bj1[4];
    #pragma unroll
    for (int j = 0; j < 4; j++) {
        bj0[j] = __ldg(&bout[v0 + 4 * tx + j]);
        bj1[j] = __ldg(&bout[v0 + 64 + 4 * tx + j]);
    }
    #pragma unroll
    for (int i = 0; i < 4; i++) {
        size_t base = (size_t)(4 * ty + i) * NV + v0;
        float4 o0, o1;
        o0.x = acc0[i][0] + bj0[0]; o0.y = acc0[i][1] + bj0[1];
        o0.z = acc0[i][2] + bj0[2]; o0.w = acc0[i][3] + bj0[3];
        o1.x = acc1[i][0] + bj1[0]; o1.y = acc1[i][1] + bj1[1];
        o1.z = acc1[i][2] + bj1[2]; o1.w = acc1[i][3] + bj1[3];
        *(float4*)&out[base + 4 * tx]      = o0;
        *(float4*)&out[base + 64 + 4 * tx] = o1;
    }
}

// ============================================================================
extern "C" void kernel_launch(void* const* d_in, const int* in_sizes, int n_in,
                              void* d_out, int out_size)
{
    const int*   seq   = (const int*)d_in[0];
    const float* embed = (const float*)d_in[1];
    const float* W1    = (const float*)d_in[2];
    const float* b1    = (const float*)d_in[3];
    const float* W2    = (const float*)d_in[4];
    const float* b2    = (const float*)d_in[5];
    const float* gamma = (const float*)d_in[6];
    const float* beta  = (const float*)d_in[7];
    const float* Wsem  = (const float*)d_in[8];
    const float* Wepi  = (const float*)d_in[9];
    const float* Wrp   = (const float*)d_in[10];
    const float* brp   = (const float*)d_in[11];
    const float* Wout  = (const float*)d_in[12];
    const float* bout  = (const float*)d_in[13];
    float* out = (float*)d_out;

    cudaFuncSetAttribute(k1_kernel, cudaFuncAttributeMaxDynamicSharedMemorySize,
                         K1_SMEMF * (int)sizeof(float));
    cudaFuncSetAttribute(k3_kernel, cudaFuncAttributeMaxDynamicSharedMemorySize,
                         K3_SMEMF * (int)sizeof(float));

    k1_kernel<<<NV / 64, 256, K1_SMEMF * sizeof(float)>>>(
        embed, W1, b1, W2, b2, gamma, beta, Wsem, Wepi);
    k2_kernel<<<NB, 256>>>(seq, Wrp, brp);
    k3_kernel<<<NV / 128, 256, K3_SMEMF * sizeof(float)>>>(Wout, bout, out);
}

// round 5
// speedup vs baseline: 1.5828x; 1.5828x over previous
#include <cuda_runtime.h>
#include <cuda_bf16.h>

#define NV 32000
#define NB 64
#define NL 1024
#define NH 128

// scratch (no allocs allowed)
__device__ float  g_tab[NV * NH];   // [v][128]: ks in 0..63, ke in 64..127
__device__ float2 g_nrm[NV];        // per-vocab (||ks||^2, ||ke||^2)
__device__ float  g_r[NB * NH];     // [b][128]

// ============================================================================
// K1: vocab table. Per CTA: 64 vocab rows, 256 threads, 85KB smem -> 2 CTA/SM.
//   E -> per-panel T1p = relu(E@W1p^T+b1p) -> X += T1p@W2p^T  (X in registers)
//   -> +E +b2 -> LN -> KK = HLN@Wk^T -> g_tab, row norms -> g_nrm
// Layout: k-major strips with odd stride 65 (conflict-free staging + reads),
// B-operand column mapping c = 16j + tx (stride-1 lanes, conflict-free).
// ============================================================================
#define K1_XS   0
#define K1_T1   8320            // [64][65]
#define K1_WB   12480           // [128][65] (W1p / Wk)  or  [64][129] (W2 slice)
#define K1_RED  20800           // [512]
#define K1_SMEMF 21312          // floats = 85248 bytes

__global__ void __launch_bounds__(256, 2)
k1_kernel(const float* __restrict__ embed,
          const float* __restrict__ W1, const float* __restrict__ b1,
          const float* __restrict__ W2, const float* __restrict__ b2,
          const float* __restrict__ gamma, const float* __restrict__ beta,
          const float* __restrict__ Wsem, const float* __restrict__ Wepi)
{
    extern __shared__ float sm[];
    float* Xs  = sm + K1_XS;    // [h(0..127)][65] : E, later X/HLN (k-major)
    float* T1p = sm + K1_T1;    // [c(0..63)][65]  : T1 panel (k-major)
    float* Wb  = sm + K1_WB;    // weight staging (shared W1p/W2slice/Wk)
    float* red = sm + K1_RED;

    const int tid = threadIdx.x;
    const int v0  = blockIdx.x * 64;
    const int ty  = tid >> 4, tx = tid & 15;

    // stage E (transposed, k-major)
    for (int idx = tid; idx < 64 * 128; idx += 256) {
        int r = idx >> 7, h = idx & 127;
        Xs[h * 65 + r] = __ldg(&embed[(size_t)(v0 + r) * NH + h]);
    }
    __syncthreads();

    // X accumulators: rows 4ty..4ty+3, cols 16j+tx (j=0..7). Init E + b2.
    float xacc[4][8];
    #pragma unroll
    for (int j = 0; j < 8; j++) {
        float bj = __ldg(&b2[16 * j + tx]);
        #pragma unroll
        for (int i = 0; i < 4; i++)
            xacc[i][j] = Xs[(16 * j + tx) * 65 + 4 * ty + i] + bj;
    }

    // ---- FFN: 4 panels of 64 hidden cols ----
    for (int p = 0; p < 4; p++) {
        // load W1 panel k-major: Wb[k][c] c=0..63
        for (int idx = tid; idx < 64 * 128; idx += 256) {
            int k = idx & 127, c = idx >> 7;
            Wb[k * 65 + c] = __ldg(&W1[(p * 64 + c) * NH + k]);
        }
        __syncthreads();

        // T1p = relu(E @ W1p^T + b1p): 64x64, thread tile 4x4 (cols 16j+tx)
        float t1[4][4];
        #pragma unroll
        for (int i = 0; i < 4; i++)
            #pragma unroll
            for (int j = 0; j < 4; j++) t1[i][j] = 0.f;
        #pragma unroll 8
        for (int k = 0; k < 128; k++) {
            float a[4], b[4];
            #pragma unroll
            for (int i = 0; i < 4; i++) a[i] = Xs[k * 65 + 4 * ty + i];
            #pragma unroll
            for (int j = 0; j < 4; j++) b[j] = Wb[k * 65 + 16 * j + tx];
            #pragma unroll
            for (int i = 0; i < 4; i++)
                #pragma unroll
                for (int j = 0; j < 4; j++) t1[i][j] += a[i] * b[j];
        }
        #pragma unroll
        for (int j = 0; j < 4; j++) {
            int c = 16 * j + tx;
            float bj = __ldg(&b1[p * 64 + c]);
            #pragma unroll
            for (int i = 0; i < 4; i++)
                T1p[c * 65 + 4 * ty + i] = fmaxf(t1[i][j] + bj, 0.f);
        }
        __syncthreads();

        // load W2 slice: rows k = 64p..64p+63 of W2^T for all 128 outputs
        for (int idx = tid; idx < 64 * 128; idx += 256) {
            int kk = idx & 63, c = idx >> 6;
            Wb[kk * 129 + c] = __ldg(&W2[c * 256 + p * 64 + kk]);
        }
        __syncthreads();

        // X += T1p @ W2slice^T : thread tile 4x8 (cols 16j+tx)
        #pragma unroll 8
        for (int kk = 0; kk < 64; kk++) {
            float a[4], b[8];
            #pragma unroll
            for (int i = 0; i < 4; i++) a[i] = T1p[kk * 65 + 4 * ty + i];
            #pragma unroll
            for (int j = 0; j < 8; j++) b[j] = Wb[kk * 129 + 16 * j + tx];
            #pragma unroll
            for (int i = 0; i < 4; i++)
                #pragma unroll
                for (int j = 0; j < 8; j++) xacc[i][j] += a[i] * b[j];
        }
        __syncthreads();   // before next panel overwrites Wb / T1p
    }

    // write X back into Xs (k-major)
    #pragma unroll
    for (int j = 0; j < 8; j++)
        #pragma unroll
        for (int i = 0; i < 4; i++)
            Xs[(16 * j + tx) * 65 + 4 * ty + i] = xacc[i][j];
    __syncthreads();

    // ---- LayerNorm in place (population var) ----
    {
        int r = tid & 63, qq = tid >> 6;
        float s1 = 0.f, s2 = 0.f;
        #pragma unroll 8
        for (int hh = 0; hh < 32; hh++) {
            float x = Xs[(qq * 32 + hh) * 65 + r];
            s1 += x; s2 += x * x;
        }
        red[qq * 64 + r]       = s1;
        red[256 + qq * 64 + r] = s2;
        __syncthreads();
        float S1 = red[r] + red[64 + r] + red[128 + r] + red[192 + r];
        float S2 = red[256 + r] + red[320 + r] + red[384 + r] + red[448 + r];
        float mu   = S1 * (1.f / 128.f);
        float var  = S2 * (1.f / 128.f) - mu * mu;
        float rstd = rsqrtf(var + 1e-5f);
        #pragma unroll 8
        for (int hh = 0; hh < 32; hh++) {
            int h = qq * 32 + hh;
            float x = Xs[h * 65 + r];
            Xs[h * 65 + r] = (x - mu) * rstd * __ldg(&gamma[h]) + __ldg(&beta[h]);
        }
    }
    __syncthreads();

    // ---- KK = HLN @ Wk^T -> g_tab, and row norms -> g_nrm ----
    for (int p = 0; p < 2; p++) {
        const float* Wk = p ? Wepi : Wsem;
        for (int idx = tid; idx < 64 * 128; idx += 256) {
            int k = idx & 127, c = idx >> 7;
            Wb[k * 65 + c] = __ldg(&Wk[c * NH + k]);
        }
        __syncthreads();
        float acc[4][4];
        #pragma unroll
        for (int i = 0; i < 4; i++)
            #pragma unroll
            for (int j = 0; j < 4; j++) acc[i][j] = 0.f;
        #pragma unroll 8
        for (int k = 0; k < 128; k++) {
            float a[4], b[4];
            #pragma unroll
            for (int i = 0; i < 4; i++) a[i] = Xs[k * 65 + 4 * ty + i];
            #pragma unroll
            for (int j = 0; j < 4; j++) b[j] = Wb[k * 65 + 16 * j + tx];
            #pragma unroll
            for (int i = 0; i < 4; i++)
                #pragma unroll
                for (int j = 0; j < 4; j++) acc[i][j] += a[i] * b[j];
        }
        // outputs
        #pragma unroll
        for (int i = 0; i < 4; i++)
            #pragma unroll
            for (int j = 0; j < 4; j++)
                g_tab[(size_t)(v0 + 4 * ty + i) * NH + p * 64 + 16 * j + tx] =
                    acc[i][j];
        // row norm^2: reduce over tx (lane bits 0..3)
        #pragma unroll
        for (int i = 0; i < 4; i++) {
            float s = acc[i][0] * acc[i][0] + acc[i][1] * acc[i][1]
                    + acc[i][2] * acc[i][2] + acc[i][3] * acc[i][3];
            s += __shfl_xor_sync(0xffffffffu, s, 1);
            s += __shfl_xor_sync(0xffffffffu, s, 2);
            s += __shfl_xor_sync(0xffffffffu, s, 4);
            s += __shfl_xor_sync(0xffffffffu, s, 8);
            if (tx == 0) {
                float* gn = (float*)&g_nrm[v0 + 4 * ty + i];
                gn[p] = s;
            }
        }
        __syncthreads();
    }
}

// ============================================================================
// K2: sequential gated memory scan. 64 CTAs (1/batch) x 256 threads.
// Threads 0..127: M_s (row = pt>>1, half h = pt&1, 32 cols each).
// Threads 128..255: M_e, same mapping.  Norms precomputed (g_nrm) and
// inv 1/||k|| computed one step EARLY from the prefetch -> off critical path.
// One barrier per step; slot/wred parity double-buffered.
// ============================================================================
__global__ void __launch_bounds__(256, 1)
k2_kernel(const int* __restrict__ seq,
          const float* __restrict__ Wrp, const float* __restrict__ brp)
{
    __shared__ int   seqs[NL];
    __shared__ float slot[2][128];
    __shared__ float wred[2][8];
    __shared__ float cbuf[128];

    const int tid  = threadIdx.x;
    const int b    = blockIdx.x;
    const int part = tid >> 7;          // 0 = s, 1 = e
    const int pt   = tid & 127;
    const int row  = pt >> 1;
    const int h    = pt & 1;
    const int lane = tid & 31;
    const int warp = tid >> 5;

    for (int idx = tid; idx < NL; idx += 256) seqs[idx] = seq[b * NL + idx];
    __syncthreads();

    // preload k_0 + its norms
    {
        int tok = seqs[0];
        if (tid < 128) slot[0][tid] = __ldg(&g_tab[(size_t)tok * NH + tid]);
    }
    float2 cn = __ldg(&g_nrm[seqs[0]]);     // current norms (all threads)
    float  cmy = part ? cn.y : cn.x;
    float  cinv = 1.f / fmaxf(sqrtf(cmy), 1e-12f);
    __syncthreads();

    float m[32];
    #pragma unroll
    for (int c = 0; c < 32; c++) m[c] = 0.f;

    const int kbase = part * 64 + h * 32;

    for (int t = 0; t < NL - 1; t++) {
        const int par = t & 1;
        const int nt  = t + 1;

        // prefetch k_{t+1} and its norms; compute next inv off critical path
        float pv = 0.f;
        if (tid < 128) pv = __ldg(&g_tab[(size_t)seqs[nt] * NH + tid]);
        float2 pn  = __ldg(&g_nrm[seqs[nt]]);
        float  pmy = part ? pn.y : pn.x;
        float  pinv = 1.f / fmaxf(sqrtf(pmy), 1e-12f);

        // load my 32 k values
        float kv[32];
        const float* kb = &slot[par][kbase];
        #pragma unroll
        for (int c = 0; c < 8; c++) {
            float4 f = *(const float4*)&kb[4 * c];
            kv[4 * c] = f.x; kv[4 * c + 1] = f.y;
            kv[4 * c + 2] = f.z; kv[4 * c + 3] = f.w;
        }

        // matvec partial (4-way split accumulation)
        float p0 = 0.f, p1 = 0.f, p2 = 0.f, p3 = 0.f;
        #pragma unroll
        for (int c = 0; c < 8; c++) {
            p0 += m[4 * c]     * kv[4 * c];
            p1 += m[4 * c + 1] * kv[4 * c + 1];
            p2 += m[4 * c + 2] * kv[4 * c + 2];
            p3 += m[4 * c + 3] * kv[4 * c + 3];
        }
        float pp = (p0 + p1) + (p2 + p3);
        pp += __shfl_xor_sync(0xffffffffu, pp, 1);      // combine halves

        float kelem = slot[par][part * 64 + row];
        float dd = kelem - pp * cinv;

        // err^2 reduce: contributing lanes are h==0 (even lanes), 4 levels
        float v = (h == 0) ? dd * dd : 0.f;
        v += __shfl_xor_sync(0xffffffffu, v, 2);
        v += __shfl_xor_sync(0xffffffffu, v, 4);
        v += __shfl_xor_sync(0xffffffffu, v, 8);
        v += __shfl_xor_sync(0xffffffffu, v, 16);
        if (lane == 0) wred[par][warp] = v;

        // commit prefetched k_{t+1} (opposite parity buffer)
        if (tid < 128) slot[nt & 1][tid] = pv;

        __syncthreads();    // the only barrier in the step

        float4 w0 = *(const float4*)&wred[par][0];
        float4 w1 = *(const float4*)&wred[par][4];
        float es2 = (w0.x + w0.y) + (w0.z + w0.w);
        float ee2 = (w1.x + w1.y) + (w1.z + w1.w);
        bool fire = (es2 >= (0.7f * 0.7f) * cn.x) ||
                    (ee2 >= (0.7f * 0.7f) * cn.y);
        float wf   = part ? ((float)nt * (1.f / (float)NL)) : 1.f;
        float coef = (fire ? 0.05f : 0.f) * wf * cinv * dd;
        #pragma unroll
        for (int c = 0; c < 32; c++) m[c] += coef * kv[c];

        // roll prefetched norms into current
        cn = pn; cinv = pinv;
    }

    // final: q = tab row of seq[b][L-1], sits in slot[1]. c = M @ q-part (raw).
    {
        const float* kb = &slot[1][kbase];
        float p0 = 0.f, p1 = 0.f, p2 = 0.f, p3 = 0.f;
        #pragma unroll
        for (int c = 0; c < 8; c++) {
            float4 f = *(const float4*)&kb[4 * c];
            p0 += m[4 * c]     * f.x;
            p1 += m[4 * c + 1] * f.y;
            p2 += m[4 * c + 2] * f.z;
            p3 += m[4 * c + 3] * f.w;
        }
        float pp = (p0 + p1) + (p2 + p3);
        pp += __shfl_xor_sync(0xffffffffu, pp, 1);
        if (h == 0) cbuf[part * 64 + row] = pp;
    }
    __syncthreads();

    // r = Wrp @ c + brp -> g_r
    {
        int o = tid >> 1, h2 = tid & 1;
        const float* wr = &Wrp[o * NH + h2 * 64];
        const float* cc = &cbuf[h2 * 64];
        float s = 0.f;
        #pragma unroll 8
        for (int mm = 0; mm < 64; mm++) s += __ldg(&wr[mm]) * cc[mm];
        s += __shfl_xor_sync(0xffffffffu, s, 1);
        if (h2 == 0) g_r[b * NH + o] = s + __ldg(&brp[o]);
    }
}

// ============================================================================
// K3: out[64 x 32000] = r @ Wout^T + bout.  250 CTAs, tile 64b x 128v.
// ============================================================================
#define K3_RST 65
#define K3_WST 129
#define K3_WS  (128 * K3_RST)
#define K3_SMEMF (K3_WS + 128 * K3_WST)

__global__ void __launch_bounds__(256, 2)
k3_kernel(const float* __restrict__ Wout, const float* __restrict__ bout,
          float* __restrict__ out)
{
    extern __shared__ float sm[];
    float* rs = sm;             // [k][65] : r transposed
    float* Ws = sm + K3_WS;     // [k][129]: Wout tile transposed
    const int tid = threadIdx.x;
    const int v0  = blockIdx.x * 128;
    const int ty  = tid >> 4, tx = tid & 15;

    for (int idx = tid; idx < 64 * 128; idx += 256) {
        int bb = idx >> 7, k = idx & 127;
        rs[k * K3_RST + bb] = g_r[idx];
    }
    for (int idx = tid; idx < 128 * 128; idx += 256) {
        int vv = idx >> 7, k = idx & 127;
        Ws[k * K3_WST + vv] = __ldg(&Wout[(size_t)(v0 + vv) * NH + k]);
    }
    __syncthreads();

    float acc0[4][4], acc1[4][4];
    #pragma unroll
    for (int i = 0; i < 4; i++)
        #pragma unroll
        for (int j = 0; j < 4; j++) { acc0[i][j] = 0.f; acc1[i][j] = 0.f; }

    #pragma unroll 4
    for (int k = 0; k < 128; k++) {
        float a[4], b0[4], b1[4];
        #pragma unroll
        for (int i = 0; i < 4; i++) a[i]  = rs[k * K3_RST + 4 * ty + i];
        #pragma unroll
        for (int j = 0; j < 4; j++) b0[j] = Ws[k * K3_WST + 16 * j + tx];
        #pragma unroll
        for (int j = 0; j < 4; j++) b1[j] = Ws[k * K3_WST + 64 + 16 * j + tx];
        #pragma unroll
        for (int i = 0; i < 4; i++)
            #pragma unroll
            for (int j = 0; j < 4; j++) {
                acc0[i][j] += a[i] * b0[j];
                acc1[i][j] += a[i] * b1[j];
            }
    }

    #pragma unroll
    for (int j = 0; j < 4; j++) {
        float bj0 = __ldg(&bout[v0 + 16 * j + tx]);
        float bj1 = __ldg(&bout[v0 + 64 + 16 * j + tx]);
        #pragma unroll
        for (int i = 0; i < 4; i++) {
            size_t base = (size_t)(4 * ty + i) * NV + v0;
            out[base + 16 * j + tx]      = acc0[i][j] + bj0;
            out[base + 64 + 16 * j + tx] = acc1[i][j] + bj1;
        }
    }
}

// ============================================================================
extern "C" void kernel_launch(void* const* d_in, const int* in_sizes, int n_in,
                              void* d_out, int out_size)
{
    const int*   seq   = (const int*)d_in[0];
    const float* embed = (const float*)d_in[1];
    const float* W1    = (const float*)d_in[2];
    const float* b1    = (const float*)d_in[3];
    const float* W2    = (const float*)d_in[4];
    const float* b2    = (const float*)d_in[5];
    const float* gamma = (const float*)d_in[6];
    const float* beta  = (const float*)d_in[7];
    const float* Wsem  = (const float*)d_in[8];
    const float* Wepi  = (const float*)d_in[9];
    const float* Wrp   = (const float*)d_in[10];
    const float* brp   = (const float*)d_in[11];
    const float* Wout  = (const float*)d_in[12];
    const float* bout  = (const float*)d_in[13];
    float* out = (float*)d_out;

    cudaFuncSetAttribute(k1_kernel, cudaFuncAttributeMaxDynamicSharedMemorySize,
                         K1_SMEMF * (int)sizeof(float));
    cudaFuncSetAttribute(k3_kernel, cudaFuncAttributeMaxDynamicSharedMemorySize,
                         K3_SMEMF * (int)sizeof(float));

    k1_kernel<<<NV / 64, 256, K1_SMEMF * sizeof(float)>>>(
        embed, W1, b1, W2, b2, gamma, beta, Wsem, Wepi);
    k2_kernel<<<NB, 256>>>(seq, Wrp, brp);
    k3_kernel<<<NV / 128, 256, K3_SMEMF * sizeof(float)>>>(Wout, bout, out);
}